// round 3
// baseline (speedup 1.0000x reference)
#include <cuda_runtime.h>
#include <cstdint>

#define B_    256
#define T_    512
#define D_    256
#define K_    256
#define BT_   (B_ * T_)
#define TK_   ((size_t)T_ * K_)

// 128 MiB scratch for the precomputed input projection xU[B*T, K]
__device__ float g_xU[(size_t)BT_ * K_];

// ---------------- packed f32x2 helpers (sm_103a FFMA2) ----------------------
__device__ __forceinline__ uint64_t pk2(float x, float y) {
    uint64_t r; asm("mov.b64 %0, {%1, %2};" : "=l"(r) : "f"(x), "f"(y)); return r;
}
__device__ __forceinline__ void upk2(uint64_t v, float& x, float& y) {
    asm("mov.b64 {%0, %1}, %2;" : "=f"(x), "=f"(y) : "l"(v));
}
__device__ __forceinline__ uint64_t ffma2(uint64_t a, uint64_t b, uint64_t c) {
    uint64_t d; asm("fma.rn.f32x2 %0, %1, %2, %3;" : "=l"(d) : "l"(a), "l"(b), "l"(c)); return d;
}
__device__ __forceinline__ void lds_v2u64(uint32_t addr, uint64_t& a, uint64_t& b) {
    asm volatile("ld.shared.v2.u64 {%0, %1}, [%2];" : "=l"(a), "=l"(b) : "r"(addr));
}
__device__ __forceinline__ uint32_t smem_u32(const void* p) {
    return (uint32_t)__cvta_generic_to_shared(p);
}

// ---------------------------------------------------------------------------
// Phase A: g_xU[m, n] = sum_k X[m, k] * U[k, n] + bias[n]
// 128x128 tile, BK=8, 256 threads, 8x8 microtile, FFMA2 core,
// 2-stage smem double buffering (one __syncthreads per k-iter).
// ---------------------------------------------------------------------------
__global__ __launch_bounds__(256, 2) void xu_gemm(const float* __restrict__ X,
                                                  const float* __restrict__ U,
                                                  const float* __restrict__ bias) {
    __shared__ float As[2][8][128];   // transposed X tile: As[buf][k][m]
    __shared__ float Bs[2][8][128];   // U tile: Bs[buf][k][n]

    const int tid  = threadIdx.x;
    const int mblk = blockIdx.x * 128;
    const int nblk = blockIdx.y * 128;

    const int aRow = tid >> 1;         // 0..127
    const int aCol = (tid & 1) * 4;    // 0 or 4
    const int bRow = tid >> 5;         // 0..7
    const int bCol = (tid & 31) * 4;   // 0..124

    const int ty = tid >> 4;           // 0..15
    const int tx = tid & 15;           // 0..15

    const float* Xp = X + (size_t)(mblk + aRow) * D_ + aCol;
    const float* Up = U + (size_t)bRow * K_ + nblk + bCol;

    const uint32_t bs_base = smem_u32(&Bs[0][0][0]);

    uint64_t acc2[8][4];               // acc2[i][jp] = cols (2jp, 2jp+1) of row i
#pragma unroll
    for (int i = 0; i < 8; i++)
#pragma unroll
        for (int j = 0; j < 4; j++) acc2[i][j] = 0ull;

    // prologue: stage k0=0 into buffer 0
    {
        float4 a4 = *(const float4*)(Xp);
        float4 b4 = *(const float4*)(Up);
        As[0][aCol + 0][aRow] = a4.x;
        As[0][aCol + 1][aRow] = a4.y;
        As[0][aCol + 2][aRow] = a4.z;
        As[0][aCol + 3][aRow] = a4.w;
        *(float4*)(&Bs[0][bRow][bCol]) = b4;
    }
    __syncthreads();

    int p = 0;
    for (int k0 = 0; k0 < D_; k0 += 8) {
        float4 a4n, b4n;
        const bool more = (k0 + 8 < D_);
        if (more) {
            a4n = *(const float4*)(Xp + k0 + 8);
            b4n = *(const float4*)(Up + (size_t)(k0 + 8) * K_);
        }
#pragma unroll
        for (int kk = 0; kk < 8; kk++) {
            float a[8];
            *(float4*)(a)     = *(const float4*)(&As[p][kk][ty * 8]);
            *(float4*)(a + 4) = *(const float4*)(&As[p][kk][ty * 8 + 4]);
            uint64_t bp[4];
            const uint32_t baddr = bs_base + (uint32_t)(p * 1024 + kk * 128 + tx * 8) * 4u;
            lds_v2u64(baddr,       bp[0], bp[1]);
            lds_v2u64(baddr + 16u, bp[2], bp[3]);
#pragma unroll
            for (int i = 0; i < 8; i++) {
                const uint64_t ap = pk2(a[i], a[i]);
#pragma unroll
                for (int jp = 0; jp < 4; jp++)
                    acc2[i][jp] = ffma2(ap, bp[jp], acc2[i][jp]);
            }
        }
        if (more) {
            const int q = p ^ 1;
            As[q][aCol + 0][aRow] = a4n.x;
            As[q][aCol + 1][aRow] = a4n.y;
            As[q][aCol + 2][aRow] = a4n.z;
            As[q][aCol + 3][aRow] = a4n.w;
            *(float4*)(&Bs[q][bRow][bCol]) = b4n;
            __syncthreads();
            p = q;
        }
    }

    // epilogue: + bias, store
    float bvals[8];
#pragma unroll
    for (int j = 0; j < 8; j++) bvals[j] = bias[nblk + tx * 8 + j];
#pragma unroll
    for (int i = 0; i < 8; i++) {
        const size_t row = (size_t)(mblk + ty * 8 + i);
        float* Cp = g_xU + row * K_ + nblk + tx * 8;
        float v[8];
#pragma unroll
        for (int jp = 0; jp < 4; jp++) upk2(acc2[i][jp], v[2 * jp], v[2 * jp + 1]);
#pragma unroll
        for (int j = 0; j < 8; j += 4) {
            float4 o;
            o.x = v[j + 0] + bvals[j + 0];
            o.y = v[j + 1] + bvals[j + 1];
            o.z = v[j + 2] + bvals[j + 2];
            o.w = v[j + 3] + bvals[j + 3];
            *(float4*)(Cp + j) = o;
        }
    }
}

// ---------------------------------------------------------------------------
// Phase B: recurrence. 64 clusters of 2 CTAs; each cluster owns 4 batch rows.
// Thread pair (2c, 2c+1) produces hidden column myd = rank*128 + c; each
// thread sums a d-half (dh = tid&1), split into 64 LOCALLY-produced d's
// followed by 64 PEER-produced d's. The cluster-barrier wait sits between the
// two halves, hiding its ~490-cyc latency under the local compute.
// Pair reduction via one butterfly shfl (each lane sends the pair its partner
// finalizes); each lane then owns 2 batch rows through tanh + stores.
// ---------------------------------------------------------------------------
__global__ void __cluster_dims__(2, 1, 1) __launch_bounds__(256, 1)
rnn_scan(const float* __restrict__ W, float* __restrict__ out) {
    __shared__ float hs[2][1024];      // hs[buf][d*4 + r]

    const int tid = threadIdx.x;
    const int dh  = tid & 1;           // which d-half this thread sums
    const int c   = tid >> 1;          // 0..127: column within this CTA's half

    uint32_t rank;
    asm("mov.u32 %0, %%cluster_ctarank;" : "=r"(rank));
    const uint32_t peer = rank ^ 1u;
    const int b0  = (blockIdx.x >> 1) * 4;   // first batch row of this cluster
    const int myd = (int)rank * 128 + c;     // hidden index this thread-pair produces

    const int dloc = (int)rank * 128 + dh * 64;   // locally-produced d range start
    const int drem = (int)peer * 128 + dh * 64;   // peer-produced d range start

    // ---- W regs: local 64 first, then remote 64 ----
    float w[128];
    {
        const float* Wl = W + (size_t)dloc * K_ + myd;
        const float* Wr = W + (size_t)drem * K_ + myd;
#pragma unroll
        for (int j = 0; j < 64; j++) w[j]      = Wl[(size_t)j * K_];
#pragma unroll
        for (int j = 0; j < 64; j++) w[64 + j] = Wr[(size_t)j * K_];
    }

    // zero both h buffers (h0 = 0)
    for (int i = tid; i < 2048; i += 256) ((float*)hs)[i] = 0.0f;
    __syncthreads();
    asm volatile("barrier.cluster.arrive.aligned;" ::: "memory");   // init arrive (phase 0)

    const uint32_t hs_local = smem_u32(&hs[0][0]);
    uint32_t hs_peer;
    asm("mapa.shared::cluster.u32 %0, %1, %2;" : "=r"(hs_peer) : "r"(hs_local), "r"(peer));

    // this thread finalizes batch rows (2dh, 2dh+1)
    const float* xbase = g_xU + (size_t)b0 * TK_ + myd;
    const size_t rA = (size_t)(dh * 2)     * TK_;
    const size_t rB = (size_t)(dh * 2 + 1) * TK_;

    float xuA = xbase[rA];
    float xuB = xbase[rB];

    for (int t = 0; t < T_; t++) {
        const uint32_t buf   = (uint32_t)(t & 1) * 4096u;
        const uint32_t bloc  = hs_local + buf + (uint32_t)dloc * 16u;
        const uint32_t brem  = hs_local + buf + (uint32_t)drem * 16u;

        uint64_t acc01 = 0ull, acc23 = 0ull;

        // ---- local 64 d's (own CTA's columns; guarded by __syncthreads) ----
#pragma unroll
        for (int j = 0; j < 64; j++) {
            uint64_t h01, h23;
            lds_v2u64(bloc + (uint32_t)j * 16u, h01, h23);
            const uint64_t wp = pk2(w[j], w[j]);
            acc01 = ffma2(h01, wp, acc01);
            acc23 = ffma2(h23, wp, acc23);
        }

        // ---- peer h_t now required: wait (hidden under local compute) ----
        asm volatile("barrier.cluster.wait.aligned;" ::: "memory");

        // ---- remote 64 d's (peer's columns) ----
#pragma unroll
        for (int j = 0; j < 64; j++) {
            uint64_t h01, h23;
            lds_v2u64(brem + (uint32_t)j * 16u, h01, h23);
            const uint64_t wp = pk2(w[64 + j], w[64 + j]);
            acc01 = ffma2(h01, wp, acc01);
            acc23 = ffma2(h23, wp, acc23);
        }

        // ---- butterfly pair-reduction: send partner the pair IT finalizes ----
        // dh=0 finalizes rows (0,1) -> needs partner's acc01, sends acc23.
        // dh=1 finalizes rows (2,3) -> needs partner's acc23, sends acc01.
        const uint64_t mine = dh ? acc23 : acc01;
        const uint64_t send = dh ? acc01 : acc23;
        float s0, s1; upk2(send, s0, s1);
        const float r0 = __shfl_xor_sync(0xffffffffu, s0, 1);
        const float r1 = __shfl_xor_sync(0xffffffffu, s1, 1);
        float m0, m1; upk2(mine, m0, m1);

        const float va = tanhf(m0 + r0 + xuA);
        const float vb = tanhf(m1 + r1 + xuB);

        if (t < T_ - 1) {
            const uint32_t wb = (uint32_t)(((t + 1) & 1) * 4096) +
                                (uint32_t)(myd * 4 + dh * 2) * 4u;
            const uint64_t vpk = pk2(va, vb);
            asm volatile("st.shared.u64 [%0], %1;"
                         :: "r"(hs_local + wb), "l"(vpk) : "memory");
            asm volatile("st.shared::cluster.u64 [%0], %1;"
                         :: "r"(hs_peer + wb), "l"(vpk) : "memory");
            // release peer store; peer's wait(t+1) acquires it
            asm volatile("barrier.cluster.arrive.aligned;" ::: "memory");
        } else {
            out[(size_t)(b0 + dh * 2)     * K_ + myd] = va;
            out[(size_t)(b0 + dh * 2 + 1) * K_ + myd] = vb;
        }

        // local h visibility for next step's local-half compute
        __syncthreads();

        // prefetch next step's xU under the sync/compute
        if (t + 1 < T_) {
            const float* xp = xbase + (size_t)(t + 1) * K_;
            xuA = xp[rA];
            xuB = xp[rB];
        }
    }
}

// ---------------------------------------------------------------------------
extern "C" void kernel_launch(void* const* d_in, const int* in_sizes, int n_in,
                              void* d_out, int out_size) {
    const float* X    = (const float*)d_in[0];  // [B,T,D]
    const float* U    = (const float*)d_in[1];  // [D,K]
    const float* W    = (const float*)d_in[2];  // [K,K]
    const float* bias = (const float*)d_in[3];  // [K]
    float* out = (float*)d_out;                 // [B,1,K]

    // Phase A: xU = X @ U + b
    dim3 g1(BT_ / 128, K_ / 128);
    xu_gemm<<<g1, 256>>>(X, U, bias);

    // Phase B: persistent cluster recurrence
    rnn_scan<<<128, 256>>>(W, out);
}

// round 5
// speedup vs baseline: 1.0077x; 1.0077x over previous
#include <cuda_runtime.h>
#include <cstdint>

#define B_    256
#define T_    512
#define D_    256
#define K_    256
#define BT_   (B_ * T_)
#define TK_   ((size_t)T_ * K_)

// 128 MiB scratch for the precomputed input projection xU[B*T, K]
__device__ float g_xU[(size_t)BT_ * K_];

// ---------------- packed f32x2 helpers (sm_103a FFMA2) ----------------------
__device__ __forceinline__ uint64_t pk2(float x, float y) {
    uint64_t r; asm("mov.b64 %0, {%1, %2};" : "=l"(r) : "f"(x), "f"(y)); return r;
}
__device__ __forceinline__ void upk2(uint64_t v, float& x, float& y) {
    asm("mov.b64 {%0, %1}, %2;" : "=f"(x), "=f"(y) : "l"(v));
}
__device__ __forceinline__ uint64_t ffma2(uint64_t a, uint64_t b, uint64_t c) {
    uint64_t d; asm("fma.rn.f32x2 %0, %1, %2, %3;" : "=l"(d) : "l"(a), "l"(b), "l"(c)); return d;
}
__device__ __forceinline__ uint64_t fadd2(uint64_t a, uint64_t b) {
    uint64_t d; asm("add.rn.f32x2 %0, %1, %2;" : "=l"(d) : "l"(a), "l"(b)); return d;
}
__device__ __forceinline__ void lds_v2u64(uint32_t addr, uint64_t& a, uint64_t& b) {
    asm volatile("ld.shared.v2.u64 {%0, %1}, [%2];" : "=l"(a), "=l"(b) : "r"(addr));
}
__device__ __forceinline__ uint32_t smem_u32(const void* p) {
    return (uint32_t)__cvta_generic_to_shared(p);
}

// fast, accurate-enough tanh: 1 - 2/(1 + e^{2x}) via MUFU ex2/rcp (~1e-6 abs err)
__device__ __forceinline__ float tanh_fast(float x) {
    float e;
    asm("ex2.approx.f32 %0, %1;" : "=f"(e) : "f"(x * 2.8853900817779268f));
    float r;
    asm("rcp.approx.f32 %0, %1;" : "=f"(r) : "f"(1.0f + e));
    return fmaf(-2.0f, r, 1.0f);
}

// ---------------------------------------------------------------------------
// Phase A: g_xU[m, n] = sum_k X[m, k] * U[k, n] + bias[n]
// 128x128 tile, BK=8, 256 threads, 8x8 per-thread microtile, FFMA2 core.
// (exact R2 version — known ~405 us)
// ---------------------------------------------------------------------------
__global__ __launch_bounds__(256) void xu_gemm(const float* __restrict__ X,
                                               const float* __restrict__ U,
                                               const float* __restrict__ bias) {
    __shared__ float As[8][128];   // transposed X tile: As[k][m]
    __shared__ float Bs[8][128];   // U tile: Bs[k][n]

    const int tid  = threadIdx.x;
    const int mblk = blockIdx.x * 128;
    const int nblk = blockIdx.y * 128;

    const int aRow = tid >> 1;         // 0..127
    const int aCol = (tid & 1) * 4;    // 0 or 4
    const int bRow = tid >> 5;         // 0..7
    const int bCol = (tid & 31) * 4;   // 0..124

    const int ty = tid >> 4;           // 0..15
    const int tx = tid & 15;           // 0..15

    const float* Xp = X + (size_t)(mblk + aRow) * D_ + aCol;
    const float* Up = U + (size_t)bRow * K_ + nblk + bCol;

    const uint32_t bs_base = smem_u32(&Bs[0][0]);

    uint64_t acc2[8][4];               // acc2[i][jp] = cols (2jp, 2jp+1) of row i
#pragma unroll
    for (int i = 0; i < 8; i++)
#pragma unroll
        for (int j = 0; j < 4; j++) acc2[i][j] = 0ull;

    for (int k0 = 0; k0 < D_; k0 += 8) {
        float4 a4 = *(const float4*)(Xp + k0);
        float4 b4 = *(const float4*)(Up + (size_t)k0 * K_);
        __syncthreads();
        As[aCol + 0][aRow] = a4.x;
        As[aCol + 1][aRow] = a4.y;
        As[aCol + 2][aRow] = a4.z;
        As[aCol + 3][aRow] = a4.w;
        *(float4*)(&Bs[bRow][bCol]) = b4;
        __syncthreads();
#pragma unroll
        for (int kk = 0; kk < 8; kk++) {
            float a[8];
            *(float4*)(a)     = *(const float4*)(&As[kk][ty * 8]);
            *(float4*)(a + 4) = *(const float4*)(&As[kk][ty * 8 + 4]);
            uint64_t bp[4];
            const uint32_t baddr = bs_base + (uint32_t)(kk * 128 + tx * 8) * 4u;
            lds_v2u64(baddr,       bp[0], bp[1]);
            lds_v2u64(baddr + 16u, bp[2], bp[3]);
#pragma unroll
            for (int i = 0; i < 8; i++) {
                const uint64_t ap = pk2(a[i], a[i]);
#pragma unroll
                for (int jp = 0; jp < 4; jp++)
                    acc2[i][jp] = ffma2(ap, bp[jp], acc2[i][jp]);
            }
        }
    }

    // epilogue: + bias, store
    float bvals[8];
#pragma unroll
    for (int j = 0; j < 8; j++) bvals[j] = bias[nblk + tx * 8 + j];
#pragma unroll
    for (int i = 0; i < 8; i++) {
        const size_t row = (size_t)(mblk + ty * 8 + i);
        float* Cp = g_xU + row * K_ + nblk + tx * 8;
        float v[8];
#pragma unroll
        for (int jp = 0; jp < 4; jp++) upk2(acc2[i][jp], v[2 * jp], v[2 * jp + 1]);
#pragma unroll
        for (int j = 0; j < 8; j += 4) {
            float4 o;
            o.x = v[j + 0] + bvals[j + 0];
            o.y = v[j + 1] + bvals[j + 1];
            o.z = v[j + 2] + bvals[j + 2];
            o.w = v[j + 3] + bvals[j + 3];
            *(float4*)(Cp + j) = o;
        }
    }
}

// ---------------------------------------------------------------------------
// Phase B: recurrence. 64 clusters of 2 CTAs; each cluster owns 4 batch rows.
// R2 skeleton: full 128-d loop, then epilogue, then arrive -> xU prefetch ->
// wait at step end. Deltas vs R2:
//   * lane-interleaved layout (dh = tid&1) so the pair reduction is ONE
//     butterfly shfl (no STS/__syncthreads/LDS round-trip)
//   * 4 accumulator chains (halved FFMA2 dependency depth)
//   * MUFU-based tanh (ex2+rcp), ~1e-6 abs error
// ---------------------------------------------------------------------------
__global__ void __cluster_dims__(2, 1, 1) __launch_bounds__(256, 1)
rnn_scan(const float* __restrict__ W, float* __restrict__ out) {
    __shared__ float hs[2][1024];      // hs[buf][d*4 + r]

    const int tid = threadIdx.x;
    const int dh  = tid & 1;           // which 128-d half this thread sums
    const int c   = tid >> 1;          // 0..127: column within this CTA's half

    uint32_t rank;
    asm("mov.u32 %0, %%cluster_ctarank;" : "=r"(rank));
    const uint32_t peer = rank ^ 1u;
    const int b0  = (blockIdx.x >> 1) * 4;   // first batch row of this cluster
    const int myd = (int)rank * 128 + c;     // hidden column this thread-pair produces

    // ---- W regs: w[j] = W[dh*128 + j][myd] ----
    float w[128];
    {
        const float* Wg = W + (size_t)(dh * 128) * K_ + myd;
#pragma unroll
        for (int j = 0; j < 128; j++) w[j] = Wg[(size_t)j * K_];
    }

    // zero both h buffers (h0 = 0)
    for (int i = tid; i < 2048; i += 256) ((float*)hs)[i] = 0.0f;
    __syncthreads();
    asm volatile("barrier.cluster.arrive.aligned;" ::: "memory");
    asm volatile("barrier.cluster.wait.aligned;"   ::: "memory");

    const uint32_t hs_local = smem_u32(&hs[0][0]);
    uint32_t hs_peer;
    asm("mapa.shared::cluster.u32 %0, %1, %2;" : "=r"(hs_peer) : "r"(hs_local), "r"(peer));

    // this thread finalizes batch rows (2dh, 2dh+1) of column myd
    const float* xbase = g_xU + (size_t)b0 * TK_ + myd;
    const size_t rA = (size_t)(dh * 2)     * TK_;
    const size_t rB = (size_t)(dh * 2 + 1) * TK_;

    float xuA = xbase[rA];
    float xuB = xbase[rB];

    for (int t = 0; t < T_; t++) {
        // ---- matvec over this thread's 128-d half, 4 chains ----
        uint64_t a01a = 0ull, a23a = 0ull, a01b = 0ull, a23b = 0ull;
        const uint32_t hb = hs_local + (uint32_t)(t & 1) * 4096u + (uint32_t)(dh * 128) * 16u;
#pragma unroll
        for (int j = 0; j < 64; j++) {
            uint64_t h01, h23;
            lds_v2u64(hb + (uint32_t)j * 16u, h01, h23);
            const uint64_t wp = pk2(w[j], w[j]);
            a01a = ffma2(h01, wp, a01a);
            a23a = ffma2(h23, wp, a23a);
            uint64_t g01, g23;
            lds_v2u64(hb + 1024u + (uint32_t)j * 16u, g01, g23);
            const uint64_t wq = pk2(w[64 + j], w[64 + j]);
            a01b = ffma2(g01, wq, a01b);
            a23b = ffma2(g23, wq, a23b);
        }
        const uint64_t acc01 = fadd2(a01a, a01b);
        const uint64_t acc23 = fadd2(a23a, a23b);

        // ---- butterfly pair-reduction with lane^1 partner (other dh) ----
        // dh=0 finalizes rows (0,1): keeps acc01, sends acc23.
        // dh=1 finalizes rows (2,3): keeps acc23, sends acc01.
        const uint64_t mine = dh ? acc23 : acc01;
        const uint64_t send = dh ? acc01 : acc23;
        float s0, s1; upk2(send, s0, s1);
        const float r0 = __shfl_xor_sync(0xffffffffu, s0, 1);
        const float r1 = __shfl_xor_sync(0xffffffffu, s1, 1);
        float m0, m1; upk2(mine, m0, m1);

        const float va = tanh_fast(m0 + r0 + xuA);
        const float vb = tanh_fast(m1 + r1 + xuB);

        if (t < T_ - 1) {
            const uint32_t wb = (uint32_t)(((t + 1) & 1) * 4096) +
                                (uint32_t)(myd * 4 + dh * 2) * 4u;
            const uint64_t vpk = pk2(va, vb);
            asm volatile("st.shared.u64 [%0], %1;"
                         :: "r"(hs_local + wb), "l"(vpk) : "memory");
            asm volatile("st.shared::cluster.u64 [%0], %1;"
                         :: "r"(hs_peer + wb), "l"(vpk) : "memory");
        } else {
            out[(size_t)(b0 + dh * 2)     * K_ + myd] = va;
            out[(size_t)(b0 + dh * 2 + 1) * K_ + myd] = vb;
        }

        // release own+peer writes; prefetch next step's xU under barrier latency
        asm volatile("barrier.cluster.arrive.aligned;" ::: "memory");
        if (t + 1 < T_) {
            const float* xp = xbase + (size_t)(t + 1) * K_;
            xuA = xp[rA];
            xuB = xp[rB];
        }
        asm volatile("barrier.cluster.wait.aligned;" ::: "memory");
    }
}

// ---------------------------------------------------------------------------
extern "C" void kernel_launch(void* const* d_in, const int* in_sizes, int n_in,
                              void* d_out, int out_size) {
    const float* X    = (const float*)d_in[0];  // [B,T,D]
    const float* U    = (const float*)d_in[1];  // [D,K]
    const float* W    = (const float*)d_in[2];  // [K,K]
    const float* bias = (const float*)d_in[3];  // [K]
    float* out = (float*)d_out;                 // [B,1,K]

    // Phase A: xU = X @ U + b
    dim3 g1(BT_ / 128, K_ / 128);
    xu_gemm<<<g1, 256>>>(X, U, bias);

    // Phase B: persistent cluster recurrence
    rnn_scan<<<128, 256>>>(W, out);
}